// round 14
// baseline (speedup 1.0000x reference)
#include <cuda_runtime.h>
#include <cuda_bf16.h>
#include <cstdint>
#include <cstddef>

#define SLEN 2048
#define BDIM 128
#define NBATCH 32
#define INV_TEMP 0.08838834764831845f   // 1/sqrt(128)

// ======================= device scratch (no cudaMalloc) ====================
__device__ __nv_bfloat16 g_q_hi[(size_t)NBATCH * SLEN * BDIM];
__device__ __nv_bfloat16 g_q_lo[(size_t)NBATCH * SLEN * BDIM];
__device__ __nv_bfloat16 g_k_hi[(size_t)NBATCH * SLEN * BDIM];
__device__ __nv_bfloat16 g_k_lo[(size_t)NBATCH * SLEN * BDIM];
__device__ __nv_bfloat16 g_vt_hi[(size_t)NBATCH * BDIM * SLEN];
__device__ __nv_bfloat16 g_vt_lo[(size_t)NBATCH * BDIM * SLEN];
__device__ float g_rowsum[(size_t)NBATCH * SLEN];

// =========================== helpers =======================================
__device__ __forceinline__ uint32_t smem_u32(const void* p) {
    uint32_t a;
    asm("{ .reg .u64 t; cvta.to.shared.u64 t, %1; cvt.u32.u64 %0, t; }"
        : "=r"(a) : "l"(p));
    return a;
}

#define LDSM_X4(r0, r1, r2, r3, addr) \
    asm volatile("ldmatrix.sync.aligned.m8n8.x4.shared.b16 {%0,%1,%2,%3}, [%4];" \
        : "=r"(r0), "=r"(r1), "=r"(r2), "=r"(r3) : "r"(addr))

#define MMA_BF16(c, a0, a1, a2, a3, b0, b1) \
    asm volatile("mma.sync.aligned.m16n8k16.row.col.f32.bf16.bf16.f32 " \
        "{%0,%1,%2,%3}, {%4,%5,%6,%7}, {%8,%9}, {%0,%1,%2,%3};" \
        : "+f"((c)[0]), "+f"((c)[1]), "+f"((c)[2]), "+f"((c)[3]) \
        : "r"(a0), "r"(a1), "r"(a2), "r"(a3), "r"(b0), "r"(b1))

#define CP_ASYNC16(dst, src) \
    asm volatile("cp.async.cg.shared.global [%0], [%1], 16;" \
        :: "r"(dst), "l"(src) : "memory")
#define CP_COMMIT  asm volatile("cp.async.commit_group;" ::: "memory")
#define CP_WAIT(n) asm volatile("cp.async.wait_group %0;" :: "n"(n) : "memory")

template <int STRIDE>
__device__ __forceinline__ void load_a_frag(uint32_t base, int mrow, int k0,
                                            int lane, uint32_t* a) {
    uint32_t off = (uint32_t)((mrow + (lane & 15)) * STRIDE + k0 + ((lane >> 4) << 3));
    LDSM_X4(a[0], a[1], a[2], a[3], base + (off << 1));
}

template <int STRIDE>
__device__ __forceinline__ void load_b_pair(uint32_t base, int nrow, int k0,
                                            int lane, uint32_t* b) {
    int g = lane >> 3;
    uint32_t off = (uint32_t)((nrow + ((g & 2) << 2) + (lane & 7)) * STRIDE
                              + k0 + ((g & 1) << 3));
    LDSM_X4(b[0], b[1], b[2], b[3], base + (off << 1));
}

__device__ __forceinline__ void cvt8(const float4& x0, const float4& x1,
                                     uint4& hi, uint4& lo) {
    float v[8] = {x0.x, x0.y, x0.z, x0.w, x1.x, x1.y, x1.z, x1.w};
    uint32_t hb[8], lb[8];
#pragma unroll
    for (int j = 0; j < 8; j++) {
        __nv_bfloat16 h = __float2bfloat16(v[j]);
        float r = v[j] - __bfloat162float(h);
        __nv_bfloat16 l = __float2bfloat16(r);
        hb[j] = (uint32_t)__bfloat16_as_ushort(h);
        lb[j] = (uint32_t)__bfloat16_as_ushort(l);
    }
    hi = make_uint4(hb[0] | (hb[1] << 16), hb[2] | (hb[3] << 16),
                    hb[4] | (hb[5] << 16), hb[6] | (hb[7] << 16));
    lo = make_uint4(lb[0] | (lb[1] << 16), lb[2] | (lb[3] << 16),
                    lb[4] | (lb[5] << 16), lb[6] | (lb[7] << 16));
}

__device__ __forceinline__ float fast_exp(float x) {
    x = fmaxf(x, -87.0f);
    float y = x * 1.4426950408889634f;
    float t = y + 12582912.0f;
    int   ni = __float_as_int(t) - 0x4B400000;
    float nf = t - 12582912.0f;
    float f = y - nf;
    float p = 1.5403530e-4f;
    p = fmaf(p, f, 1.3333558e-3f);
    p = fmaf(p, f, 9.6181291e-3f);
    p = fmaf(p, f, 5.5504109e-2f);
    p = fmaf(p, f, 2.4022651e-1f);
    p = fmaf(p, f, 6.9314718e-1f);
    p = fmaf(p, f, 1.0f);
    return p * __int_as_float((ni + 127) << 23);
}

// ===== rowsum kernel tile geometry (same as R9 score) =====
#define TSTRIDE 40
#define SLICE   (128 * TSTRIDE * 2)
#define TBUF    (4 * SLICE)
#define TSMEM   (2 * TBUF)

// =============== prep: zero rowsum + split Q,K + V^T split ==================
#define PREP_SMEM (128 * 132 * 4)
__global__ __launch_bounds__(256) void prep_kernel(
    const float* __restrict__ Q, const float* __restrict__ K,
    const float* __restrict__ V)
{
    extern __shared__ float ts[];
    const int st = blockIdx.x, b = blockIdx.y, tid = threadIdx.x;
    const int s0 = st * 128;

    if (tid < 32)
        *reinterpret_cast<float4*>(g_rowsum + (size_t)b * SLEN + s0 + tid * 4) =
            make_float4(0.f, 0.f, 0.f, 0.f);

    const size_t base0 = ((size_t)b * SLEN + s0) * BDIM;
#pragma unroll
    for (int i = 0; i < 8; i++) {
        const size_t off = base0 + (size_t)(tid + i * 256) * 8;
        uint4 hi, lo;
        float4 x0 = *reinterpret_cast<const float4*>(Q + off);
        float4 x1 = *reinterpret_cast<const float4*>(Q + off + 4);
        cvt8(x0, x1, hi, lo);
        *reinterpret_cast<uint4*>(g_q_hi + off) = hi;
        *reinterpret_cast<uint4*>(g_q_lo + off) = lo;
        x0 = *reinterpret_cast<const float4*>(K + off);
        x1 = *reinterpret_cast<const float4*>(K + off + 4);
        cvt8(x0, x1, hi, lo);
        *reinterpret_cast<uint4*>(g_k_hi + off) = hi;
        *reinterpret_cast<uint4*>(g_k_lo + off) = lo;
    }

    const float* vg = V + base0;
#pragma unroll
    for (int i = 0; i < 16; i++) {
        int flat = tid + i * 256;
        int row = flat >> 5, c4 = flat & 31;
        float4 x = *reinterpret_cast<const float4*>(vg + (size_t)row * BDIM + c4 * 4);
        *reinterpret_cast<float4*>(ts + row * 132 + c4 * 4) = x;
    }
    __syncthreads();
#pragma unroll
    for (int i = 0; i < 8; i++) {
        int flat = tid + i * 256;
        int d = flat >> 4, sg = (flat & 15) * 8;
        uint32_t hb[8], lb[8];
#pragma unroll
        for (int j = 0; j < 8; j++) {
            float v = ts[(sg + j) * 132 + d];
            __nv_bfloat16 h = __float2bfloat16(v);
            float r = v - __bfloat162float(h);
            __nv_bfloat16 l = __float2bfloat16(r);
            hb[j] = (uint32_t)__bfloat16_as_ushort(h);
            lb[j] = (uint32_t)__bfloat16_as_ushort(l);
        }
        uint4 hi = make_uint4(hb[0] | (hb[1] << 16), hb[2] | (hb[3] << 16),
                              hb[4] | (hb[5] << 16), hb[6] | (hb[7] << 16));
        uint4 lo = make_uint4(lb[0] | (lb[1] << 16), lb[2] | (lb[3] << 16),
                              lb[4] | (lb[5] << 16), lb[6] | (lb[7] << 16));
        size_t idx = ((size_t)b * BDIM + d) * SLEN + s0 + sg;
        *reinterpret_cast<uint4*>(g_vt_hi + idx) = hi;
        *reinterpret_cast<uint4*>(g_vt_lo + idx) = lo;
    }
}

// ===== kernel 1: rowsums of exp(causal(QK^T/sqrt(D))) + zero upper tiles ====
__global__ __launch_bounds__(256, 2) void rowsum_kernel(float* __restrict__ attn)
{
    extern __shared__ char sm[];
    const int kt = blockIdx.x, qt = blockIdx.y, b = blockIdx.z;
    const int tid = threadIdx.x, wid = tid >> 5, lane = tid & 31;

    if (kt > qt) {   // fully masked tile -> zeros
        float* out = attn + (size_t)b * SLEN * SLEN + (size_t)(qt * 128) * SLEN + kt * 128;
        const float4 z = make_float4(0.f, 0.f, 0.f, 0.f);
#pragma unroll
        for (int it = 0; it < 16; it++) {
            const int flat = tid + it * 256;
            const int r = flat >> 5, c4 = flat & 31;
            *reinterpret_cast<float4*>(out + (size_t)r * SLEN + c4 * 4) = z;
        }
        return;
    }

    const uint32_t sb = smem_u32(sm);
    const size_t qoff = ((size_t)b * SLEN + qt * 128) * BDIM;
    const size_t koff = ((size_t)b * SLEN + kt * 128) * BDIM;
    const __nv_bfloat16* srcs[4] = {g_q_hi + qoff, g_q_lo + qoff,
                                    g_k_hi + koff, g_k_lo + koff};

    auto fill = [&](int buf, int c) {
#pragma unroll
        for (int i = 0; i < 8; i++) {
            const int flat = tid + i * 256;
            const int tile = flat >> 9;
            const int idx  = flat & 511;
            const int row  = idx >> 2, u = idx & 3;
            uint32_t dst = sb + buf * TBUF + tile * SLICE
                         + (uint32_t)(row * TSTRIDE + u * 8) * 2;
            CP_ASYNC16(dst, srcs[tile] + (size_t)row * BDIM + c * 32 + u * 8);
        }
    };

    const int wm = wid & 3;
    const int wn = wid >> 2;
    const int mbase = wm * 32;
    const int nbase = wn * 64;

    float acc[2][8][4] = {};

    fill(0, 0);
    CP_COMMIT;
    for (int c = 0; c < 4; c++) {
        if (c + 1 < 4) {
            __syncthreads();
            fill((c + 1) & 1, c + 1);
            CP_COMMIT;
            CP_WAIT(1);
        } else {
            CP_WAIT(0);
        }
        __syncthreads();

        const uint32_t cb = sb + (c & 1) * TBUF;
#pragma unroll
        for (int kc = 0; kc < 2; kc++) {
            const int k0 = kc * 16;
            uint32_t ahi[2][4], alo[2][4];
#pragma unroll
            for (int mt = 0; mt < 2; mt++) {
                load_a_frag<TSTRIDE>(cb,         mbase + mt * 16, k0, lane, ahi[mt]);
                load_a_frag<TSTRIDE>(cb + SLICE, mbase + mt * 16, k0, lane, alo[mt]);
            }
#pragma unroll
            for (int jp = 0; jp < 4; jp++) {
                uint32_t bhi[4], blo[4];
                load_b_pair<TSTRIDE>(cb + 2 * SLICE, nbase + jp * 16, k0, lane, bhi);
                load_b_pair<TSTRIDE>(cb + 3 * SLICE, nbase + jp * 16, k0, lane, blo);
                const int n0 = jp * 2, n1 = jp * 2 + 1;
                MMA_BF16(acc[0][n0], ahi[0][0], ahi[0][1], ahi[0][2], ahi[0][3], bhi[0], bhi[1]);
                MMA_BF16(acc[0][n1], ahi[0][0], ahi[0][1], ahi[0][2], ahi[0][3], bhi[2], bhi[3]);
                MMA_BF16(acc[1][n0], ahi[1][0], ahi[1][1], ahi[1][2], ahi[1][3], bhi[0], bhi[1]);
                MMA_BF16(acc[1][n1], ahi[1][0], ahi[1][1], ahi[1][2], ahi[1][3], bhi[2], bhi[3]);
                MMA_BF16(acc[0][n0], ahi[0][0], ahi[0][1], ahi[0][2], ahi[0][3], blo[0], blo[1]);
                MMA_BF16(acc[0][n1], ahi[0][0], ahi[0][1], ahi[0][2], ahi[0][3], blo[2], blo[3]);
                MMA_BF16(acc[1][n0], ahi[1][0], ahi[1][1], ahi[1][2], ahi[1][3], blo[0], blo[1]);
                MMA_BF16(acc[1][n1], ahi[1][0], ahi[1][1], ahi[1][2], ahi[1][3], blo[2], blo[3]);
                MMA_BF16(acc[0][n0], alo[0][0], alo[0][1], alo[0][2], alo[0][3], bhi[0], bhi[1]);
                MMA_BF16(acc[0][n1], alo[0][0], alo[0][1], alo[0][2], alo[0][3], bhi[2], bhi[3]);
                MMA_BF16(acc[1][n0], alo[1][0], alo[1][1], alo[1][2], alo[1][3], bhi[0], bhi[1]);
                MMA_BF16(acc[1][n1], alo[1][0], alo[1][1], alo[1][2], alo[1][3], bhi[2], bhi[3]);
            }
        }
    }

    const bool diag = (kt == qt);
    float rsum[2][2] = {};
#pragma unroll
    for (int mt = 0; mt < 2; mt++) {
        const int r0 = mbase + mt * 16 + (lane >> 2);
#pragma unroll
        for (int nt = 0; nt < 8; nt++) {
            const int col = nbase + nt * 8 + (lane & 3) * 2;
#pragma unroll
            for (int h = 0; h < 2; h++) {
                const int r = r0 + h * 8;
                float v0 = fast_exp(acc[mt][nt][h * 2 + 0] * INV_TEMP);
                float v1 = fast_exp(acc[mt][nt][h * 2 + 1] * INV_TEMP);
                if (diag) {
                    if (col + 0 > r) v0 = 0.f;
                    if (col + 1 > r) v1 = 0.f;
                }
                rsum[mt][h] += v0 + v1;
            }
        }
    }
#pragma unroll
    for (int mt = 0; mt < 2; mt++)
#pragma unroll
        for (int h = 0; h < 2; h++) {
            rsum[mt][h] += __shfl_xor_sync(0xffffffffu, rsum[mt][h], 1);
            rsum[mt][h] += __shfl_xor_sync(0xffffffffu, rsum[mt][h], 2);
        }
    if ((lane & 3) == 0) {
        float* rs = g_rowsum + (size_t)b * SLEN + qt * 128;
#pragma unroll
        for (int mt = 0; mt < 2; mt++)
#pragma unroll
            for (int h = 0; h < 2; h++)
                atomicAdd(rs + mbase + mt * 16 + (lane >> 2) + h * 8, rsum[mt][h]);
    }
}

// ===== kernel 2 (fused): recompute S, write normalized E, accumulate ctx ====
// 64-query strips, 32-key chunks, 256 threads, 2 CTAs/SM.
#define FQ_STR 136
#define FP_STR 40
#define F_QHI 0
#define F_QLO 17408
#define F_KHI 34816
#define F_KLO 43520
#define F_PHI 52224
#define F_PLO 57344
#define F_VHI 62464
#define F_VLO 72704
#define F_SMEM 82944

__global__ __launch_bounds__(256, 2) void fused_kernel(
    float* __restrict__ attn, float* __restrict__ ctx)
{
    extern __shared__ char sm[];
    __shared__ float sinv[64];
    const int qh = (int)gridDim.x - 1 - blockIdx.x;   // 64-row strip, heavy first
    const int b  = blockIdx.y;
    const int tid = threadIdx.x, wid = tid >> 5, lane = tid & 31;
    const uint32_t sb = smem_u32(sm);

    if (tid < 64)
        sinv[tid] = 1.0f / g_rowsum[(size_t)b * SLEN + qh * 64 + tid];

    const size_t qoff = ((size_t)b * SLEN + qh * 64) * BDIM;
    const __nv_bfloat16* qsrc[2] = {g_q_hi + qoff, g_q_lo + qoff};
    const size_t kbase = (size_t)b * SLEN * BDIM;
    const __nv_bfloat16* ksrc[2] = {g_k_hi + kbase, g_k_lo + kbase};
    const size_t vbase = (size_t)b * BDIM * SLEN;
    const __nv_bfloat16* vsrc[2] = {g_vt_hi + vbase, g_vt_lo + vbase};

    // Q resident fill: 2 arrays x 64 rows x 16 16B units  (FIXED: full 128 cols)
#pragma unroll
    for (int i = 0; i < 8; i++) {
        int flat = tid + i * 256;            // 0..2047
        int arr = flat >> 10, idx = flat & 1023;
        int row = idx >> 4, u = idx & 15;
        CP_ASYNC16(sb + F_QHI + arr * 17408 + (uint32_t)(row * FQ_STR + u * 8) * 2,
                   qsrc[arr] + (size_t)row * BDIM + u * 8);
    }
    auto fillK = [&](int c) {
#pragma unroll
        for (int i = 0; i < 4; i++) {
            int flat = tid + i * 256;        // 0..1023  (FIXED: full 128 cols)
            int arr = flat >> 9, idx = flat & 511;
            int row = idx >> 4, u = idx & 15;
            CP_ASYNC16(sb + F_KHI + arr * 8704 + (uint32_t)(row * FQ_STR + u * 8) * 2,
                       ksrc[arr] + (size_t)(c * 32 + row) * BDIM + u * 8);
        }
    };
    auto fillV = [&](int c) {
#pragma unroll
        for (int i = 0; i < 4; i++) {
            int flat = tid + i * 256;
            int arr = flat >> 9, idx = flat & 511;
            int row = idx >> 2, u = idx & 3;
            CP_ASYNC16(sb + F_VHI + arr * 10240 + (uint32_t)(row * FP_STR + u * 8) * 2,
                       vsrc[arr] + (size_t)row * SLEN + c * 32 + u * 8);
        }
    };
    fillK(0);
    CP_COMMIT;     // group: {Q + K0}

    const int wmS = wid & 3, wnS = wid >> 2;   // S: 4x16q, 2x16k
    const int wmP = wid & 1, wnP = wid >> 1;   // PV: 2x32q, 4x32d

    float ctxa[2][4][4] = {};
    const int nch = ((qh >> 1) + 1) * 4;
    float* outr = attn + (size_t)b * SLEN * SLEN + (size_t)(qh * 64) * SLEN;

    for (int c = 0; c < nch; c++) {
        fillV(c); CP_COMMIT;
        CP_WAIT(1);                  // Q+K(c) complete, V(c) pending
        __syncthreads();

        const bool zchunk = (32 * c > qh * 64 + 63);
        const bool cmask  = (c >= 2 * qh);

        if (!zchunk) {
            float accs[2][4] = {};
#pragma unroll
            for (int kc = 0; kc < 8; kc++) {
                const int k0 = kc * 16;
                uint32_t ah[4], al[4], bh[4], bl[4];
                load_a_frag<FQ_STR>(sb + F_QHI, wmS * 16, k0, lane, ah);
                load_a_frag<FQ_STR>(sb + F_QLO, wmS * 16, k0, lane, al);
                load_b_pair<FQ_STR>(sb + F_KHI, wnS * 16, k0, lane, bh);
                load_b_pair<FQ_STR>(sb + F_KLO, wnS * 16, k0, lane, bl);
                MMA_BF16(accs[0], ah[0], ah[1], ah[2], ah[3], bh[0], bh[1]);
                MMA_BF16(accs[1], ah[0], ah[1], ah[2], ah[3], bh[2], bh[3]);
                MMA_BF16(accs[0], ah[0], ah[1], ah[2], ah[3], bl[0], bl[1]);
                MMA_BF16(accs[1], ah[0], ah[1], ah[2], ah[3], bl[2], bl[3]);
                MMA_BF16(accs[0], al[0], al[1], al[2], al[3], bh[0], bh[1]);
                MMA_BF16(accs[1], al[0], al[1], al[2], al[3], bh[2], bh[3]);
            }
#pragma unroll
            for (int nt = 0; nt < 2; nt++) {
                const int cl = wnS * 16 + nt * 8 + (lane & 3) * 2;
#pragma unroll
                for (int h = 0; h < 2; h++) {
                    const int r = wmS * 16 + (lane >> 2) + h * 8;
                    float v0 = fast_exp(accs[nt][h * 2 + 0] * INV_TEMP) * sinv[r];
                    float v1 = fast_exp(accs[nt][h * 2 + 1] * INV_TEMP) * sinv[r];
                    if (cmask) {
                        if (c * 32 + cl + 0 > qh * 64 + r) v0 = 0.f;
                        if (c * 32 + cl + 1 > qh * 64 + r) v1 = 0.f;
                    }
                    *reinterpret_cast<float2*>(outr + (size_t)r * SLEN + c * 32 + cl) =
                        make_float2(v0, v1);
                    __nv_bfloat16 h0 = __float2bfloat16(v0), h1 = __float2bfloat16(v1);
                    float r0f = v0 - __bfloat162float(h0);
                    float r1f = v1 - __bfloat162float(h1);
                    __nv_bfloat16 l0 = __float2bfloat16(r0f), l1 = __float2bfloat16(r1f);
                    uint32_t ph = (uint32_t)__bfloat16_as_ushort(h0)
                                | ((uint32_t)__bfloat16_as_ushort(h1) << 16);
                    uint32_t pl = (uint32_t)__bfloat16_as_ushort(l0)
                                | ((uint32_t)__bfloat16_as_ushort(l1) << 16);
                    *reinterpret_cast<uint32_t*>(sm + F_PHI + (uint32_t)(r * FP_STR + cl) * 2) = ph;
                    *reinterpret_cast<uint32_t*>(sm + F_PLO + (uint32_t)(r * FP_STR + cl) * 2) = pl;
                }
            }
        } else {
            const float4 z = make_float4(0.f, 0.f, 0.f, 0.f);
#pragma unroll
            for (int i = 0; i < 2; i++) {
                int flat = tid + i * 256;
                int r = flat >> 3, c4 = flat & 7;
                *reinterpret_cast<float4*>(outr + (size_t)r * SLEN + c * 32 + c4 * 4) = z;
            }
        }

        __syncthreads();
        if (c + 1 < nch) { fillK(c + 1); CP_COMMIT; CP_WAIT(1); }
        else             { CP_WAIT(0); }
        __syncthreads();

        if (!zchunk) {
#pragma unroll
            for (int kc = 0; kc < 2; kc++) {
                const int k0 = kc * 16;
                uint32_t ah[2][4], al[2][4];
#pragma unroll
                for (int mt = 0; mt < 2; mt++) {
                    load_a_frag<FP_STR>(sb + F_PHI, wmP * 32 + mt * 16, k0, lane, ah[mt]);
                    load_a_frag<FP_STR>(sb + F_PLO, wmP * 32 + mt * 16, k0, lane, al[mt]);
                }
#pragma unroll
                for (int jp = 0; jp < 2; jp++) {
                    uint32_t bh[4], bl[4];
                    load_b_pair<FP_STR>(sb + F_VHI, wnP * 32 + jp * 16, k0, lane, bh);
                    load_b_pair<FP_STR>(sb + F_VLO, wnP * 32 + jp * 16, k0, lane, bl);
                    const int n0 = jp * 2, n1 = jp * 2 + 1;
                    MMA_BF16(ctxa[0][n0], ah[0][0], ah[0][1], ah[0][2], ah[0][3], bh[0], bh[1]);
                    MMA_BF16(ctxa[0][n1], ah[0][0], ah[0][1], ah[0][2], ah[0][3], bh[2], bh[3]);
                    MMA_BF16(ctxa[1][n0], ah[1][0], ah[1][1], ah[1][2], ah[1][3], bh[0], bh[1]);
                    MMA_BF16(ctxa[1][n1], ah[1][0], ah[1][1], ah[1][2], ah[1][3], bh[2], bh[3]);
                    MMA_BF16(ctxa[0][n0], ah[0][0], ah[0][1], ah[0][2], ah[0][3], bl[0], bl[1]);
                    MMA_BF16(ctxa[0][n1], ah[0][0], ah[0][1], ah[0][2], ah[0][3], bl[2], bl[3]);
                    MMA_BF16(ctxa[1][n0], ah[1][0], ah[1][1], ah[1][2], ah[1][3], bl[0], bl[1]);
                    MMA_BF16(ctxa[1][n1], ah[1][0], ah[1][1], ah[1][2], ah[1][3], bl[2], bl[3]);
                    MMA_BF16(ctxa[0][n0], al[0][0], al[0][1], al[0][2], al[0][3], bh[0], bh[1]);
                    MMA_BF16(ctxa[0][n1], al[0][0], al[0][1], al[0][2], al[0][3], bh[2], bh[3]);
                    MMA_BF16(ctxa[1][n0], al[1][0], al[1][1], al[1][2], al[1][3], bh[0], bh[1]);
                    MMA_BF16(ctxa[1][n1], al[1][0], al[1][1], al[1][2], al[1][3], bh[2], bh[3]);
                }
            }
        }
        __syncthreads();
    }

    float* og = ctx + ((size_t)b * SLEN + qh * 64) * BDIM;
#pragma unroll
    for (int mt = 0; mt < 2; mt++) {
        const int r = wmP * 32 + mt * 16 + (lane >> 2);
#pragma unroll
        for (int nt = 0; nt < 4; nt++) {
            const int col = wnP * 32 + nt * 8 + (lane & 3) * 2;
#pragma unroll
            for (int h = 0; h < 2; h++) {
                *reinterpret_cast<float2*>(og + (size_t)(r + h * 8) * BDIM + col) =
                    make_float2(ctxa[mt][nt][h * 2], ctxa[mt][nt][h * 2 + 1]);
            }
        }
    }
}

// ============================== launch ======================================
extern "C" void kernel_launch(void* const* d_in, const int* in_sizes, int n_in,
                              void* d_out, int out_size)
{
    const float* q = (const float*)d_in[0];
    const float* k = (const float*)d_in[1];
    const float* v = (const float*)d_in[2];

    float* ctx  = (float*)d_out;
    float* attn = ctx + (size_t)NBATCH * SLEN * BDIM;

    cudaFuncSetAttribute(prep_kernel,   cudaFuncAttributeMaxDynamicSharedMemorySize, PREP_SMEM);
    cudaFuncSetAttribute(rowsum_kernel, cudaFuncAttributeMaxDynamicSharedMemorySize, TSMEM);
    cudaFuncSetAttribute(fused_kernel,  cudaFuncAttributeMaxDynamicSharedMemorySize, F_SMEM);

    prep_kernel<<<dim3(SLEN / 128, NBATCH), 256, PREP_SMEM>>>(q, k, v);
    rowsum_kernel<<<dim3(SLEN / 128, SLEN / 128, NBATCH), 256, TSMEM>>>(attn);
    fused_kernel<<<dim3(SLEN / 64, NBATCH), 256, F_SMEM>>>(attn, ctx);
}

// round 15
// speedup vs baseline: 1.3391x; 1.3391x over previous
#include <cuda_runtime.h>
#include <cuda_bf16.h>
#include <cstdint>
#include <cstddef>

#define SLEN 2048
#define BDIM 128
#define NBATCH 32
#define INV_TEMP 0.08838834764831845f   // 1/sqrt(128)

// ======================= device scratch (no cudaMalloc) ====================
__device__ __nv_bfloat16 g_q_hi[(size_t)NBATCH * SLEN * BDIM];
__device__ __nv_bfloat16 g_q_lo[(size_t)NBATCH * SLEN * BDIM];
__device__ __nv_bfloat16 g_k_hi[(size_t)NBATCH * SLEN * BDIM];
__device__ __nv_bfloat16 g_k_lo[(size_t)NBATCH * SLEN * BDIM];
__device__ __nv_bfloat16 g_vt_hi[(size_t)NBATCH * BDIM * SLEN];
__device__ __nv_bfloat16 g_vt_lo[(size_t)NBATCH * BDIM * SLEN];
__device__ float g_rowsum[(size_t)NBATCH * SLEN];

// =========================== helpers =======================================
__device__ __forceinline__ uint32_t smem_u32(const void* p) {
    uint32_t a;
    asm("{ .reg .u64 t; cvta.to.shared.u64 t, %1; cvt.u32.u64 %0, t; }"
        : "=r"(a) : "l"(p));
    return a;
}

#define LDSM_X4(r0, r1, r2, r3, addr) \
    asm volatile("ldmatrix.sync.aligned.m8n8.x4.shared.b16 {%0,%1,%2,%3}, [%4];" \
        : "=r"(r0), "=r"(r1), "=r"(r2), "=r"(r3) : "r"(addr))

#define MMA_BF16(c, a0, a1, a2, a3, b0, b1) \
    asm volatile("mma.sync.aligned.m16n8k16.row.col.f32.bf16.bf16.f32 " \
        "{%0,%1,%2,%3}, {%4,%5,%6,%7}, {%8,%9}, {%0,%1,%2,%3};" \
        : "+f"((c)[0]), "+f"((c)[1]), "+f"((c)[2]), "+f"((c)[3]) \
        : "r"(a0), "r"(a1), "r"(a2), "r"(a3), "r"(b0), "r"(b1))

#define CP_ASYNC16(dst, src) \
    asm volatile("cp.async.cg.shared.global [%0], [%1], 16;" \
        :: "r"(dst), "l"(src) : "memory")
#define CP_COMMIT  asm volatile("cp.async.commit_group;" ::: "memory")
#define CP_WAIT(n) asm volatile("cp.async.wait_group %0;" :: "n"(n) : "memory")

template <int STRIDE>
__device__ __forceinline__ void load_a_frag(uint32_t base, int mrow, int k0,
                                            int lane, uint32_t* a) {
    uint32_t off = (uint32_t)((mrow + (lane & 15)) * STRIDE + k0 + ((lane >> 4) << 3));
    LDSM_X4(a[0], a[1], a[2], a[3], base + (off << 1));
}

template <int STRIDE>
__device__ __forceinline__ void load_b_pair(uint32_t base, int nrow, int k0,
                                            int lane, uint32_t* b) {
    int g = lane >> 3;
    uint32_t off = (uint32_t)((nrow + ((g & 2) << 2) + (lane & 7)) * STRIDE
                              + k0 + ((g & 1) << 3));
    LDSM_X4(b[0], b[1], b[2], b[3], base + (off << 1));
}

// split 8 fp32 -> bf16 hi/lo packed uint4s
__device__ __forceinline__ void cvt8(const float4& x0, const float4& x1,
                                     uint4& hi, uint4& lo) {
    float v[8] = {x0.x, x0.y, x0.z, x0.w, x1.x, x1.y, x1.z, x1.w};
    uint32_t hb[8], lb[8];
#pragma unroll
    for (int j = 0; j < 8; j++) {
        __nv_bfloat16 h = __float2bfloat16(v[j]);
        float r = v[j] - __bfloat162float(h);
        __nv_bfloat16 l = __float2bfloat16(r);
        hb[j] = (uint32_t)__bfloat16_as_ushort(h);
        lb[j] = (uint32_t)__bfloat16_as_ushort(l);
    }
    hi = make_uint4(hb[0] | (hb[1] << 16), hb[2] | (hb[3] << 16),
                    hb[4] | (hb[5] << 16), hb[6] | (hb[7] << 16));
    lo = make_uint4(lb[0] | (lb[1] << 16), lb[2] | (lb[3] << 16),
                    lb[4] | (lb[5] << 16), lb[6] | (lb[7] << 16));
}

// fast exp on FMA/ALU pipes (no MUFU): 2^f poly deg-6, rel err ~1e-7
__device__ __forceinline__ float fast_exp(float x) {
    x = fmaxf(x, -87.0f);
    float y = x * 1.4426950408889634f;
    float t = y + 12582912.0f;
    int   ni = __float_as_int(t) - 0x4B400000;
    float nf = t - 12582912.0f;
    float f = y - nf;
    float p = 1.5403530e-4f;
    p = fmaf(p, f, 1.3333558e-3f);
    p = fmaf(p, f, 9.6181291e-3f);
    p = fmaf(p, f, 5.5504109e-2f);
    p = fmaf(p, f, 2.4022651e-1f);
    p = fmaf(p, f, 6.9314718e-1f);
    p = fmaf(p, f, 1.0f);
    return p * __int_as_float((ni + 127) << 23);
}

// shared tile geometry: K-chunks of 32, 4 slices per buffer, double buffered
#define TSTRIDE 40                          // bf16 elems per row (32 + 8 pad)
#define SLICE   (128 * TSTRIDE * 2)         // 10240 B
#define TBUF    (4 * SLICE)                 // 40960 B
#define TSMEM   (2 * TBUF)                  // 81920 B -> 2 CTAs/SM

// =============== prep 0: zero row sums + zero ctx ===========================
// total floats: 65536 rowsum + NBATCH*SLEN*BDIM ctx = 8.45M -> float4 grid
__global__ __launch_bounds__(256) void zsum_kernel(float* __restrict__ ctx) {
    const size_t i4 = ((size_t)blockIdx.x * 256 + threadIdx.x) * 4;
    const float4 z = make_float4(0.f, 0.f, 0.f, 0.f);
    const size_t ctx_elems = (size_t)NBATCH * SLEN * BDIM;
    if (i4 < ctx_elems)
        *reinterpret_cast<float4*>(ctx + i4) = z;
    else if (i4 < ctx_elems + (size_t)NBATCH * SLEN)
        *reinterpret_cast<float4*>(g_rowsum + (i4 - ctx_elems)) = z;
}

// =============== prep 1: split Q,K into bf16 hi/lo scratch ==================
__global__ __launch_bounds__(256) void split_qk_kernel(
    const float* __restrict__ Q, const float* __restrict__ K)
{
    const size_t base = ((size_t)blockIdx.x * 256 + threadIdx.x) * 8;
    uint4 hi, lo;
    float4 x0 = *reinterpret_cast<const float4*>(Q + base);
    float4 x1 = *reinterpret_cast<const float4*>(Q + base + 4);
    cvt8(x0, x1, hi, lo);
    *reinterpret_cast<uint4*>(g_q_hi + base) = hi;
    *reinterpret_cast<uint4*>(g_q_lo + base) = lo;
    x0 = *reinterpret_cast<const float4*>(K + base);
    x1 = *reinterpret_cast<const float4*>(K + base + 4);
    cvt8(x0, x1, hi, lo);
    *reinterpret_cast<uint4*>(g_k_hi + base) = hi;
    *reinterpret_cast<uint4*>(g_k_lo + base) = lo;
}

// =============== prep 2: V -> V^T bf16 hi/lo scratch ========================
#define VT_SMEM (128 * 132 * 4)
__global__ __launch_bounds__(256) void vt_kernel(const float* __restrict__ V) {
    extern __shared__ float ts[];   // [128][132]
    const int st = blockIdx.x, b = blockIdx.y, tid = threadIdx.x;
    const int s0 = st * 128;
    const float* vg = V + ((size_t)b * SLEN + s0) * BDIM;
#pragma unroll
    for (int i = 0; i < 16; i++) {
        int flat = tid + i * 256;
        int row = flat >> 5, c4 = flat & 31;
        float4 x = *reinterpret_cast<const float4*>(vg + (size_t)row * BDIM + c4 * 4);
        *reinterpret_cast<float4*>(ts + row * 132 + c4 * 4) = x;
    }
    __syncthreads();
#pragma unroll
    for (int i = 0; i < 8; i++) {
        int flat = tid + i * 256;
        int d = flat >> 4, sg = (flat & 15) * 8;
        uint32_t hb[8], lb[8];
#pragma unroll
        for (int j = 0; j < 8; j++) {
            float v = ts[(sg + j) * 132 + d];
            __nv_bfloat16 h = __float2bfloat16(v);
            float r = v - __bfloat162float(h);
            __nv_bfloat16 l = __float2bfloat16(r);
            hb[j] = (uint32_t)__bfloat16_as_ushort(h);
            lb[j] = (uint32_t)__bfloat16_as_ushort(l);
        }
        uint4 hi = make_uint4(hb[0] | (hb[1] << 16), hb[2] | (hb[3] << 16),
                              hb[4] | (hb[5] << 16), hb[6] | (hb[7] << 16));
        uint4 lo = make_uint4(lb[0] | (lb[1] << 16), lb[2] | (lb[3] << 16),
                              lb[4] | (lb[5] << 16), lb[6] | (lb[7] << 16));
        size_t idx = ((size_t)b * BDIM + d) * SLEN + s0 + sg;
        *reinterpret_cast<uint4*>(g_vt_hi + idx) = hi;
        *reinterpret_cast<uint4*>(g_vt_lo + idx) = lo;
    }
}

// ====== kernel 1: E = exp(causal(QK^T/sqrt(D))) + per-row sum atomics =======
// 256 threads, 2 CTAs/SM, warp tile 32x64, double-buffered k-chunks of 32
__global__ __launch_bounds__(256, 2) void score_kernel(float* __restrict__ attn)
{
    extern __shared__ char sm[];
    const int kt = blockIdx.x, qt = blockIdx.y, b = blockIdx.z;
    const int tid = threadIdx.x, wid = tid >> 5, lane = tid & 31;

    float* out = attn + (size_t)b * SLEN * SLEN + (size_t)(qt * 128) * SLEN + kt * 128;

    if (kt > qt) {   // fully masked tile -> zeros
        const float4 z = make_float4(0.f, 0.f, 0.f, 0.f);
#pragma unroll
        for (int it = 0; it < 16; it++) {
            const int flat = tid + it * 256;
            const int r = flat >> 5, c4 = flat & 31;
            *reinterpret_cast<float4*>(out + (size_t)r * SLEN + c4 * 4) = z;
        }
        return;
    }

    const uint32_t sb = smem_u32(sm);
    const size_t qoff = ((size_t)b * SLEN + qt * 128) * BDIM;
    const size_t koff = ((size_t)b * SLEN + kt * 128) * BDIM;
    const __nv_bfloat16* srcs[4] = {g_q_hi + qoff, g_q_lo + qoff,
                                    g_k_hi + koff, g_k_lo + koff};

    auto fill = [&](int buf, int c) {
#pragma unroll
        for (int i = 0; i < 8; i++) {
            const int flat = tid + i * 256;
            const int tile = flat >> 9;
            const int idx  = flat & 511;
            const int row  = idx >> 2, u = idx & 3;
            uint32_t dst = sb + buf * TBUF + tile * SLICE
                         + (uint32_t)(row * TSTRIDE + u * 8) * 2;
            CP_ASYNC16(dst, srcs[tile] + (size_t)row * BDIM + c * 32 + u * 8);
        }
    };

    const int wm = wid & 3;
    const int wn = wid >> 2;
    const int mbase = wm * 32;
    const int nbase = wn * 64;

    float acc[2][8][4] = {};

    fill(0, 0);
    CP_COMMIT;
    for (int c = 0; c < 4; c++) {
        if (c + 1 < 4) {
            __syncthreads();
            fill((c + 1) & 1, c + 1);
            CP_COMMIT;
            CP_WAIT(1);
        } else {
            CP_WAIT(0);
        }
        __syncthreads();

        const uint32_t cb = sb + (c & 1) * TBUF;
#pragma unroll
        for (int kc = 0; kc < 2; kc++) {
            const int k0 = kc * 16;
            uint32_t ahi[2][4], alo[2][4];
#pragma unroll
            for (int mt = 0; mt < 2; mt++) {
                load_a_frag<TSTRIDE>(cb,         mbase + mt * 16, k0, lane, ahi[mt]);
                load_a_frag<TSTRIDE>(cb + SLICE, mbase + mt * 16, k0, lane, alo[mt]);
            }
#pragma unroll
            for (int jp = 0; jp < 4; jp++) {
                uint32_t bhi[4], blo[4];
                load_b_pair<TSTRIDE>(cb + 2 * SLICE, nbase + jp * 16, k0, lane, bhi);
                load_b_pair<TSTRIDE>(cb + 3 * SLICE, nbase + jp * 16, k0, lane, blo);
                const int n0 = jp * 2, n1 = jp * 2 + 1;
                MMA_BF16(acc[0][n0], ahi[0][0], ahi[0][1], ahi[0][2], ahi[0][3], bhi[0], bhi[1]);
                MMA_BF16(acc[0][n1], ahi[0][0], ahi[0][1], ahi[0][2], ahi[0][3], bhi[2], bhi[3]);
                MMA_BF16(acc[1][n0], ahi[1][0], ahi[1][1], ahi[1][2], ahi[1][3], bhi[0], bhi[1]);
                MMA_BF16(acc[1][n1], ahi[1][0], ahi[1][1], ahi[1][2], ahi[1][3], bhi[2], bhi[3]);
                MMA_BF16(acc[0][n0], ahi[0][0], ahi[0][1], ahi[0][2], ahi[0][3], blo[0], blo[1]);
                MMA_BF16(acc[0][n1], ahi[0][0], ahi[0][1], ahi[0][2], ahi[0][3], blo[2], blo[3]);
                MMA_BF16(acc[1][n0], ahi[1][0], ahi[1][1], ahi[1][2], ahi[1][3], blo[0], blo[1]);
                MMA_BF16(acc[1][n1], ahi[1][0], ahi[1][1], ahi[1][2], ahi[1][3], blo[2], blo[3]);
                MMA_BF16(acc[0][n0], alo[0][0], alo[0][1], alo[0][2], alo[0][3], bhi[0], bhi[1]);
                MMA_BF16(acc[0][n1], alo[0][0], alo[0][1], alo[0][2], alo[0][3], bhi[2], bhi[3]);
                MMA_BF16(acc[1][n0], alo[1][0], alo[1][1], alo[1][2], alo[1][3], bhi[0], bhi[1]);
                MMA_BF16(acc[1][n1], alo[1][0], alo[1][1], alo[1][2], alo[1][3], bhi[2], bhi[3]);
            }
        }
    }

    const bool diag = (kt == qt);
    float rsum[2][2] = {};
#pragma unroll
    for (int mt = 0; mt < 2; mt++) {
        const int r0 = mbase + mt * 16 + (lane >> 2);
#pragma unroll
        for (int nt = 0; nt < 8; nt++) {
            const int col = nbase + nt * 8 + (lane & 3) * 2;
#pragma unroll
            for (int h = 0; h < 2; h++) {
                const int r = r0 + h * 8;
                float v0 = fast_exp(acc[mt][nt][h * 2 + 0] * INV_TEMP);
                float v1 = fast_exp(acc[mt][nt][h * 2 + 1] * INV_TEMP);
                if (diag) {
                    if (col + 0 > r) v0 = 0.f;
                    if (col + 1 > r) v1 = 0.f;
                }
                rsum[mt][h] += v0 + v1;
                *reinterpret_cast<float2*>(out + (size_t)r * SLEN + col) =
                    make_float2(v0, v1);
            }
        }
    }
#pragma unroll
    for (int mt = 0; mt < 2; mt++)
#pragma unroll
        for (int h = 0; h < 2; h++) {
            rsum[mt][h] += __shfl_xor_sync(0xffffffffu, rsum[mt][h], 1);
            rsum[mt][h] += __shfl_xor_sync(0xffffffffu, rsum[mt][h], 2);
        }
    if ((lane & 3) == 0) {
        float* rs = g_rowsum + (size_t)b * SLEN + qt * 128;
#pragma unroll
        for (int mt = 0; mt < 2; mt++)
#pragma unroll
            for (int h = 0; h < 2; h++)
                atomicAdd(rs + mbase + mt * 16 + (lane >> 2) + h * 8, rsum[mt][h]);
    }
}

// ====== kernel 2: ctx += (E/rowsum) @ V; also writes normalized attn ========
// Key-range split: grid (2, 16, 32); each half handles (qt+1)*2 chunks of 32.
// 512 threads, 2 CTAs/SM, warp tile 32x32. ctx accumulated via atomicAdd.
__global__ __launch_bounds__(512, 2) void pv_kernel(
    float* __restrict__ attn,
    float* __restrict__ ctx)
{
    extern __shared__ char sm[];
    __shared__ float sinv[128];
    const int half = blockIdx.x;
    const int qt = 15 - (int)blockIdx.y;              // big strips first
    const int b  = blockIdx.z;
    const int tid = threadIdx.x, wid = tid >> 5, lane = tid & 31;

    const uint32_t sb = smem_u32(sm);
    float* pg = attn + (size_t)b * SLEN * SLEN + (size_t)(qt * 128) * SLEN;

    if (tid < 128)
        sinv[tid] = 1.0f / g_rowsum[(size_t)b * SLEN + qt * 128 + tid];
    __syncthreads();

    auto fill = [&](int buf, int c) {
        const int k0 = c * 32;
        char* base = sm + buf * TBUF;
        const uint32_t sbase = sb + buf * TBUF;
#pragma unroll
        for (int i = 0; i < 2; i++) {
            const int flat = tid + i * 512;
            if (flat < 512) {
                const int row = flat >> 2, g8 = (flat & 3) * 8;
                float* prow = pg + (size_t)row * SLEN + k0 + g8;
                float4 x0 = *reinterpret_cast<const float4*>(prow);
                float4 x1 = *reinterpret_cast<const float4*>(prow + 4);
                const float inv = sinv[row];
                x0.x *= inv; x0.y *= inv; x0.z *= inv; x0.w *= inv;
                x1.x *= inv; x1.y *= inv; x1.z *= inv; x1.w *= inv;
                *reinterpret_cast<float4*>(prow)     = x0;
                *reinterpret_cast<float4*>(prow + 4) = x1;
                uint4 hi, lo;
                cvt8(x0, x1, hi, lo);
                uint32_t dst = (uint32_t)(row * TSTRIDE + g8) * 2;
                *reinterpret_cast<uint4*>(base + dst)         = hi;
                *reinterpret_cast<uint4*>(base + SLICE + dst) = lo;
            } else {
                const int f = flat - 512;
                const int row = f >> 2, u = (f & 3) * 8;
                size_t vidx = ((size_t)b * BDIM + row) * SLEN + k0 + u;
                uint32_t dst = (uint32_t)(row * TSTRIDE + u) * 2;
                CP_ASYNC16(sbase + 2 * SLICE + dst, (const char*)(g_vt_hi + vidx));
                CP_ASYNC16(sbase + 3 * SLICE + dst, (const char*)(g_vt_lo + vidx));
            }
        }
    };

    const int wm = wid & 3;
    const int wn = wid >> 2;
    const int mbase = wm * 32;
    const int nbase = wn * 32;

    float acc[2][4][4] = {};
    const int cn = (qt + 1) * 2;       // chunks per half
    const int c0 = half * cn;

    fill(0, c0);
    CP_COMMIT;

    for (int i = 0; i < cn; i++) {
        if (i + 1 < cn) {
            __syncthreads();
            fill((i + 1) & 1, c0 + i + 1);
            CP_COMMIT;
            CP_WAIT(1);
        } else {
            CP_WAIT(0);
        }
        __syncthreads();

        const uint32_t cb = sb + (i & 1) * TBUF;
#pragma unroll
        for (int kc = 0; kc < 2; kc++) {
            const int k0 = kc * 16;
            uint32_t bhi[8], blo[8];
#pragma unroll
            for (int jp = 0; jp < 2; jp++) {
                load_b_pair<TSTRIDE>(cb + 2 * SLICE, nbase + jp * 16, k0, lane, &bhi[jp * 4]);
                load_b_pair<TSTRIDE>(cb + 3 * SLICE, nbase + jp * 16, k0, lane, &blo[jp * 4]);
            }
#pragma unroll
            for (int mt = 0; mt < 2; mt++) {
                uint32_t ahi[4], alo[4];
                load_a_frag<TSTRIDE>(cb, mbase + mt * 16, k0, lane, ahi);
                load_a_frag<TSTRIDE>(cb + SLICE, mbase + mt * 16, k0, lane, alo);
#pragma unroll
                for (int nt = 0; nt < 4; nt++) {
                    MMA_BF16(acc[mt][nt], ahi[0], ahi[1], ahi[2], ahi[3], bhi[nt * 2], bhi[nt * 2 + 1]);
                    MMA_BF16(acc[mt][nt], ahi[0], ahi[1], ahi[2], ahi[3], blo[nt * 2], blo[nt * 2 + 1]);
                    MMA_BF16(acc[mt][nt], alo[0], alo[1], alo[2], alo[3], bhi[nt * 2], bhi[nt * 2 + 1]);
                }
            }
        }
    }

    // accumulate ctx via atomics (2 halves contribute per output element)
    float* og = ctx + ((size_t)b * SLEN + qt * 128) * BDIM;
#pragma unroll
    for (int mt = 0; mt < 2; mt++) {
        const int r0 = mbase + mt * 16 + (lane >> 2);
#pragma unroll
        for (int nt = 0; nt < 4; nt++) {
            const int col = nbase + nt * 8 + (lane & 3) * 2;
#pragma unroll
            for (int h = 0; h < 2; h++) {
                const int r = r0 + h * 8;
                atomicAdd(og + (size_t)r * BDIM + col + 0, acc[mt][nt][h * 2 + 0]);
                atomicAdd(og + (size_t)r * BDIM + col + 1, acc[mt][nt][h * 2 + 1]);
            }
        }
    }
}

// ============================== launch ======================================
extern "C" void kernel_launch(void* const* d_in, const int* in_sizes, int n_in,
                              void* d_out, int out_size)
{
    const float* q = (const float*)d_in[0];
    const float* k = (const float*)d_in[1];
    const float* v = (const float*)d_in[2];

    float* ctx  = (float*)d_out;
    float* attn = ctx + (size_t)NBATCH * SLEN * BDIM;

    cudaFuncSetAttribute(vt_kernel,    cudaFuncAttributeMaxDynamicSharedMemorySize, VT_SMEM);
    cudaFuncSetAttribute(score_kernel, cudaFuncAttributeMaxDynamicSharedMemorySize, TSMEM);
    cudaFuncSetAttribute(pv_kernel,    cudaFuncAttributeMaxDynamicSharedMemorySize, TSMEM);

    // zero ctx (for atomics) + rowsum: (8.39M + 65K) floats / 4 per thread
    const int ztot = (NBATCH * SLEN * BDIM + NBATCH * SLEN) / 4;   // float4 count
    zsum_kernel<<<(ztot + 255) / 256, 256>>>(ctx);
    split_qk_kernel<<<(NBATCH * SLEN * BDIM) / (256 * 8), 256>>>(q, k);
    vt_kernel<<<dim3(SLEN / 128, NBATCH), 256, VT_SMEM>>>(v);
    score_kernel<<<dim3(SLEN / 128, SLEN / 128, NBATCH), 256, TSMEM>>>(attn);
    pv_kernel<<<dim3(2, SLEN / 128, NBATCH), 512, TSMEM>>>(attn, ctx);
}

// round 16
// speedup vs baseline: 1.3486x; 1.0071x over previous
#include <cuda_runtime.h>
#include <cuda_bf16.h>
#include <cstdint>
#include <cstddef>

#define SLEN 2048
#define BDIM 128
#define NBATCH 32
#define INV_TEMP 0.08838834764831845f   // 1/sqrt(128)

// ======================= device scratch (no cudaMalloc) ====================
__device__ __nv_bfloat16 g_q_hi[(size_t)NBATCH * SLEN * BDIM];
__device__ __nv_bfloat16 g_q_lo[(size_t)NBATCH * SLEN * BDIM];
__device__ __nv_bfloat16 g_k_hi[(size_t)NBATCH * SLEN * BDIM];
__device__ __nv_bfloat16 g_k_lo[(size_t)NBATCH * SLEN * BDIM];
__device__ __nv_bfloat16 g_vt_hi[(size_t)NBATCH * BDIM * SLEN];
__device__ __nv_bfloat16 g_vt_lo[(size_t)NBATCH * BDIM * SLEN];
__device__ float g_rowsum[(size_t)NBATCH * SLEN];

// =========================== helpers =======================================
__device__ __forceinline__ uint32_t smem_u32(const void* p) {
    uint32_t a;
    asm("{ .reg .u64 t; cvta.to.shared.u64 t, %1; cvt.u32.u64 %0, t; }"
        : "=r"(a) : "l"(p));
    return a;
}

#define LDSM_X4(r0, r1, r2, r3, addr) \
    asm volatile("ldmatrix.sync.aligned.m8n8.x4.shared.b16 {%0,%1,%2,%3}, [%4];" \
        : "=r"(r0), "=r"(r1), "=r"(r2), "=r"(r3) : "r"(addr))

#define MMA_BF16(c, a0, a1, a2, a3, b0, b1) \
    asm volatile("mma.sync.aligned.m16n8k16.row.col.f32.bf16.bf16.f32 " \
        "{%0,%1,%2,%3}, {%4,%5,%6,%7}, {%8,%9}, {%0,%1,%2,%3};" \
        : "+f"((c)[0]), "+f"((c)[1]), "+f"((c)[2]), "+f"((c)[3]) \
        : "r"(a0), "r"(a1), "r"(a2), "r"(a3), "r"(b0), "r"(b1))

#define CP_ASYNC16(dst, src) \
    asm volatile("cp.async.cg.shared.global [%0], [%1], 16;" \
        :: "r"(dst), "l"(src) : "memory")
#define CP_COMMIT  asm volatile("cp.async.commit_group;" ::: "memory")
#define CP_WAIT(n) asm volatile("cp.async.wait_group %0;" :: "n"(n) : "memory")

template <int STRIDE>
__device__ __forceinline__ void load_a_frag(uint32_t base, int mrow, int k0,
                                            int lane, uint32_t* a) {
    uint32_t off = (uint32_t)((mrow + (lane & 15)) * STRIDE + k0 + ((lane >> 4) << 3));
    LDSM_X4(a[0], a[1], a[2], a[3], base + (off << 1));
}

template <int STRIDE>
__device__ __forceinline__ void load_b_pair(uint32_t base, int nrow, int k0,
                                            int lane, uint32_t* b) {
    int g = lane >> 3;
    uint32_t off = (uint32_t)((nrow + ((g & 2) << 2) + (lane & 7)) * STRIDE
                              + k0 + ((g & 1) << 3));
    LDSM_X4(b[0], b[1], b[2], b[3], base + (off << 1));
}

// split 8 fp32 -> bf16 hi/lo packed uint4s
__device__ __forceinline__ void cvt8(const float4& x0, const float4& x1,
                                     uint4& hi, uint4& lo) {
    float v[8] = {x0.x, x0.y, x0.z, x0.w, x1.x, x1.y, x1.z, x1.w};
    uint32_t hb[8], lb[8];
#pragma unroll
    for (int j = 0; j < 8; j++) {
        __nv_bfloat16 h = __float2bfloat16(v[j]);
        float r = v[j] - __bfloat162float(h);
        __nv_bfloat16 l = __float2bfloat16(r);
        hb[j] = (uint32_t)__bfloat16_as_ushort(h);
        lb[j] = (uint32_t)__bfloat16_as_ushort(l);
    }
    hi = make_uint4(hb[0] | (hb[1] << 16), hb[2] | (hb[3] << 16),
                    hb[4] | (hb[5] << 16), hb[6] | (hb[7] << 16));
    lo = make_uint4(lb[0] | (lb[1] << 16), lb[2] | (lb[3] << 16),
                    lb[4] | (lb[5] << 16), lb[6] | (lb[7] << 16));
}

// fast exp on FMA/ALU pipes (no MUFU): 2^f poly deg-6, rel err ~1e-7
__device__ __forceinline__ float fast_exp(float x) {
    x = fmaxf(x, -87.0f);
    float y = x * 1.4426950408889634f;
    float t = y + 12582912.0f;
    int   ni = __float_as_int(t) - 0x4B400000;
    float nf = t - 12582912.0f;
    float f = y - nf;
    float p = 1.5403530e-4f;
    p = fmaf(p, f, 1.3333558e-3f);
    p = fmaf(p, f, 9.6181291e-3f);
    p = fmaf(p, f, 5.5504109e-2f);
    p = fmaf(p, f, 2.4022651e-1f);
    p = fmaf(p, f, 6.9314718e-1f);
    p = fmaf(p, f, 1.0f);
    return p * __int_as_float((ni + 127) << 23);
}

// key permutation inside each 16-row group: fragment slots {2g,2g+1,2g+8,2g+9}
// hold keys {4g,4g+1,4g+2,4g+3}  ->  lane stores one contiguous float4
__device__ __forceinline__ int kperm(int n) {
    return (n & ~15) | (n & 1) | (((n >> 3) & 1) << 1) | (((n >> 1) & 3) << 2);
}

// shared tile geometry: K-chunks of 32, 4 slices per buffer, double buffered
#define TSTRIDE 40                          // bf16 elems per row (32 + 8 pad)
#define SLICE   (128 * TSTRIDE * 2)         // 10240 B
#define TBUF    (4 * SLICE)                 // 40960 B
#define TSMEM   (2 * TBUF)                  // 81920 B -> 2 CTAs/SM

// =============== prep 0: zero row sums + zero ctx ===========================
__global__ __launch_bounds__(256) void zsum_kernel(float* __restrict__ ctx) {
    const size_t i4 = ((size_t)blockIdx.x * 256 + threadIdx.x) * 4;
    const float4 z = make_float4(0.f, 0.f, 0.f, 0.f);
    const size_t ctx_elems = (size_t)NBATCH * SLEN * BDIM;
    if (i4 < ctx_elems)
        *reinterpret_cast<float4*>(ctx + i4) = z;
    else if (i4 < ctx_elems + (size_t)NBATCH * SLEN)
        *reinterpret_cast<float4*>(g_rowsum + (i4 - ctx_elems)) = z;
}

// =============== prep 1: split Q,K into bf16 hi/lo scratch ==================
__global__ __launch_bounds__(256) void split_qk_kernel(
    const float* __restrict__ Q, const float* __restrict__ K)
{
    const size_t base = ((size_t)blockIdx.x * 256 + threadIdx.x) * 8;
    uint4 hi, lo;
    float4 x0 = *reinterpret_cast<const float4*>(Q + base);
    float4 x1 = *reinterpret_cast<const float4*>(Q + base + 4);
    cvt8(x0, x1, hi, lo);
    *reinterpret_cast<uint4*>(g_q_hi + base) = hi;
    *reinterpret_cast<uint4*>(g_q_lo + base) = lo;
    x0 = *reinterpret_cast<const float4*>(K + base);
    x1 = *reinterpret_cast<const float4*>(K + base + 4);
    cvt8(x0, x1, hi, lo);
    *reinterpret_cast<uint4*>(g_k_hi + base) = hi;
    *reinterpret_cast<uint4*>(g_k_lo + base) = lo;
}

// =============== prep 2: V -> V^T bf16 hi/lo scratch ========================
#define VT_SMEM (128 * 132 * 4)
__global__ __launch_bounds__(256) void vt_kernel(const float* __restrict__ V) {
    extern __shared__ float ts[];   // [128][132]
    const int st = blockIdx.x, b = blockIdx.y, tid = threadIdx.x;
    const int s0 = st * 128;
    const float* vg = V + ((size_t)b * SLEN + s0) * BDIM;
#pragma unroll
    for (int i = 0; i < 16; i++) {
        int flat = tid + i * 256;
        int row = flat >> 5, c4 = flat & 31;
        float4 x = *reinterpret_cast<const float4*>(vg + (size_t)row * BDIM + c4 * 4);
        *reinterpret_cast<float4*>(ts + row * 132 + c4 * 4) = x;
    }
    __syncthreads();
#pragma unroll
    for (int i = 0; i < 8; i++) {
        int flat = tid + i * 256;
        int d = flat >> 4, sg = (flat & 15) * 8;
        uint32_t hb[8], lb[8];
#pragma unroll
        for (int j = 0; j < 8; j++) {
            float v = ts[(sg + j) * 132 + d];
            __nv_bfloat16 h = __float2bfloat16(v);
            float r = v - __bfloat162float(h);
            __nv_bfloat16 l = __float2bfloat16(r);
            hb[j] = (uint32_t)__bfloat16_as_ushort(h);
            lb[j] = (uint32_t)__bfloat16_as_ushort(l);
        }
        uint4 hi = make_uint4(hb[0] | (hb[1] << 16), hb[2] | (hb[3] << 16),
                              hb[4] | (hb[5] << 16), hb[6] | (hb[7] << 16));
        uint4 lo = make_uint4(lb[0] | (lb[1] << 16), lb[2] | (lb[3] << 16),
                              lb[4] | (lb[5] << 16), lb[6] | (lb[7] << 16));
        size_t idx = ((size_t)b * BDIM + d) * SLEN + s0 + sg;
        *reinterpret_cast<uint4*>(g_vt_hi + idx) = hi;
        *reinterpret_cast<uint4*>(g_vt_lo + idx) = lo;
    }
}

// ====== kernel 1: E = exp(causal(QK^T/sqrt(D))) + per-row sum atomics =======
// 256 threads, 2 CTAs/SM, warp tile 32x64, double-buffered k-chunks of 32.
// K rows permuted in smem (kperm) so the epilogue emits contiguous STG.128.
__global__ __launch_bounds__(256, 2) void score_kernel(float* __restrict__ attn)
{
    extern __shared__ char sm[];
    const int kt = blockIdx.x, qt = blockIdx.y, b = blockIdx.z;
    const int tid = threadIdx.x, wid = tid >> 5, lane = tid & 31;

    float* out = attn + (size_t)b * SLEN * SLEN + (size_t)(qt * 128) * SLEN + kt * 128;

    if (kt > qt) {   // fully masked tile -> zeros
        const float4 z = make_float4(0.f, 0.f, 0.f, 0.f);
#pragma unroll
        for (int it = 0; it < 16; it++) {
            const int flat = tid + it * 256;
            const int r = flat >> 5, c4 = flat & 31;
            *reinterpret_cast<float4*>(out + (size_t)r * SLEN + c4 * 4) = z;
        }
        return;
    }

    const uint32_t sb = smem_u32(sm);
    const size_t qoff = ((size_t)b * SLEN + qt * 128) * BDIM;
    const size_t koff = ((size_t)b * SLEN + kt * 128) * BDIM;
    const __nv_bfloat16* srcs[4] = {g_q_hi + qoff, g_q_lo + qoff,
                                    g_k_hi + koff, g_k_lo + koff};

    auto fill = [&](int buf, int c) {
#pragma unroll
        for (int i = 0; i < 8; i++) {
            const int flat = tid + i * 256;
            const int tile = flat >> 9;
            const int idx  = flat & 511;
            const int row  = idx >> 2, u = idx & 3;
            // K slices (tiles 2,3): permuted source row for contiguous stores
            const int srow = (tile >= 2) ? kperm(row) : row;
            uint32_t dst = sb + buf * TBUF + tile * SLICE
                         + (uint32_t)(row * TSTRIDE + u * 8) * 2;
            CP_ASYNC16(dst, srcs[tile] + (size_t)srow * BDIM + c * 32 + u * 8);
        }
    };

    const int wm = wid & 3;
    const int wn = wid >> 2;
    const int mbase = wm * 32;
    const int nbase = wn * 64;

    float acc[2][8][4] = {};

    fill(0, 0);
    CP_COMMIT;
    for (int c = 0; c < 4; c++) {
        if (c + 1 < 4) {
            __syncthreads();
            fill((c + 1) & 1, c + 1);
            CP_COMMIT;
            CP_WAIT(1);
        } else {
            CP_WAIT(0);
        }
        __syncthreads();

        const uint32_t cb = sb + (c & 1) * TBUF;
#pragma unroll
        for (int kc = 0; kc < 2; kc++) {
            const int k0 = kc * 16;
            uint32_t ahi[2][4], alo[2][4];
#pragma unroll
            for (int mt = 0; mt < 2; mt++) {
                load_a_frag<TSTRIDE>(cb,         mbase + mt * 16, k0, lane, ahi[mt]);
                load_a_frag<TSTRIDE>(cb + SLICE, mbase + mt * 16, k0, lane, alo[mt]);
            }
#pragma unroll
            for (int jp = 0; jp < 4; jp++) {
                uint32_t bhi[4], blo[4];
                load_b_pair<TSTRIDE>(cb + 2 * SLICE, nbase + jp * 16, k0, lane, bhi);
                load_b_pair<TSTRIDE>(cb + 3 * SLICE, nbase + jp * 16, k0, lane, blo);
                const int n0 = jp * 2, n1 = jp * 2 + 1;
                MMA_BF16(acc[0][n0], ahi[0][0], ahi[0][1], ahi[0][2], ahi[0][3], bhi[0], bhi[1]);
                MMA_BF16(acc[0][n1], ahi[0][0], ahi[0][1], ahi[0][2], ahi[0][3], bhi[2], bhi[3]);
                MMA_BF16(acc[1][n0], ahi[1][0], ahi[1][1], ahi[1][2], ahi[1][3], bhi[0], bhi[1]);
                MMA_BF16(acc[1][n1], ahi[1][0], ahi[1][1], ahi[1][2], ahi[1][3], bhi[2], bhi[3]);
                MMA_BF16(acc[0][n0], ahi[0][0], ahi[0][1], ahi[0][2], ahi[0][3], blo[0], blo[1]);
                MMA_BF16(acc[0][n1], ahi[0][0], ahi[0][1], ahi[0][2], ahi[0][3], blo[2], blo[3]);
                MMA_BF16(acc[1][n0], ahi[1][0], ahi[1][1], ahi[1][2], ahi[1][3], blo[0], blo[1]);
                MMA_BF16(acc[1][n1], ahi[1][0], ahi[1][1], ahi[1][2], ahi[1][3], blo[2], blo[3]);
                MMA_BF16(acc[0][n0], alo[0][0], alo[0][1], alo[0][2], alo[0][3], bhi[0], bhi[1]);
                MMA_BF16(acc[0][n1], alo[0][0], alo[0][1], alo[0][2], alo[0][3], bhi[2], bhi[3]);
                MMA_BF16(acc[1][n0], alo[1][0], alo[1][1], alo[1][2], alo[1][3], bhi[0], bhi[1]);
                MMA_BF16(acc[1][n1], alo[1][0], alo[1][1], alo[1][2], alo[1][3], bhi[2], bhi[3]);
            }
        }
    }

    // epilogue: with kperm, lane's 4 values per (mt,jp,h) are 4 consecutive keys
    const bool diag = (kt == qt);
    float rsum[2][2] = {};
#pragma unroll
    for (int mt = 0; mt < 2; mt++) {
        const int r0 = mbase + mt * 16 + (lane >> 2);
#pragma unroll
        for (int jp = 0; jp < 4; jp++) {
            const int colb = nbase + jp * 16 + (lane & 3) * 4;   // 4 consecutive keys
            const int ne = jp * 2, no = jp * 2 + 1;
#pragma unroll
            for (int h = 0; h < 2; h++) {
                const int r = r0 + h * 8;
                float v0 = fast_exp(acc[mt][ne][h * 2 + 0] * INV_TEMP);
                float v1 = fast_exp(acc[mt][ne][h * 2 + 1] * INV_TEMP);
                float v2 = fast_exp(acc[mt][no][h * 2 + 0] * INV_TEMP);
                float v3 = fast_exp(acc[mt][no][h * 2 + 1] * INV_TEMP);
                if (diag) {
                    if (colb + 0 > r) v0 = 0.f;
                    if (colb + 1 > r) v1 = 0.f;
                    if (colb + 2 > r) v2 = 0.f;
                    if (colb + 3 > r) v3 = 0.f;
                }
                rsum[mt][h] += (v0 + v1) + (v2 + v3);
                *reinterpret_cast<float4*>(out + (size_t)r * SLEN + colb) =
                    make_float4(v0, v1, v2, v3);
            }
        }
    }
#pragma unroll
    for (int mt = 0; mt < 2; mt++)
#pragma unroll
        for (int h = 0; h < 2; h++) {
            rsum[mt][h] += __shfl_xor_sync(0xffffffffu, rsum[mt][h], 1);
            rsum[mt][h] += __shfl_xor_sync(0xffffffffu, rsum[mt][h], 2);
        }
    if ((lane & 3) == 0) {
        float* rs = g_rowsum + (size_t)b * SLEN + qt * 128;
#pragma unroll
        for (int mt = 0; mt < 2; mt++)
#pragma unroll
            for (int h = 0; h < 2; h++)
                atomicAdd(rs + mbase + mt * 16 + (lane >> 2) + h * 8, rsum[mt][h]);
    }
}

// ====== kernel 2: ctx += (E/rowsum) @ V; also writes normalized attn ========
// Key-range split: grid (2, 16, 32); each half handles (qt+1)*2 chunks of 32.
// 512 threads, 2 CTAs/SM, warp tile 32x32. ctx accumulated via atomicAdd.
__global__ __launch_bounds__(512, 2) void pv_kernel(
    float* __restrict__ attn,
    float* __restrict__ ctx)
{
    extern __shared__ char sm[];
    __shared__ float sinv[128];
    const int half = blockIdx.x;
    const int qt = 15 - (int)blockIdx.y;              // big strips first
    const int b  = blockIdx.z;
    const int tid = threadIdx.x, wid = tid >> 5, lane = tid & 31;

    const uint32_t sb = smem_u32(sm);
    float* pg = attn + (size_t)b * SLEN * SLEN + (size_t)(qt * 128) * SLEN;

    if (tid < 128)
        sinv[tid] = 1.0f / g_rowsum[(size_t)b * SLEN + qt * 128 + tid];
    __syncthreads();

    auto fill = [&](int buf, int c) {
        const int k0 = c * 32;
        char* base = sm + buf * TBUF;
        const uint32_t sbase = sb + buf * TBUF;
#pragma unroll
        for (int i = 0; i < 2; i++) {
            const int flat = tid + i * 512;
            if (flat < 512) {
                const int row = flat >> 2, g8 = (flat & 3) * 8;
                float* prow = pg + (size_t)row * SLEN + k0 + g8;
                float4 x0 = *reinterpret_cast<const float4*>(prow);
                float4 x1 = *reinterpret_cast<const float4*>(prow + 4);
                const float inv = sinv[row];
                x0.x *= inv; x0.y *= inv; x0.z *= inv; x0.w *= inv;
                x1.x *= inv; x1.y *= inv; x1.z *= inv; x1.w *= inv;
                *reinterpret_cast<float4*>(prow)     = x0;
                *reinterpret_cast<float4*>(prow + 4) = x1;
                uint4 hi, lo;
                cvt8(x0, x1, hi, lo);
                uint32_t dst = (uint32_t)(row * TSTRIDE + g8) * 2;
                *reinterpret_cast<uint4*>(base + dst)         = hi;
                *reinterpret_cast<uint4*>(base + SLICE + dst) = lo;
            } else {
                const int f = flat - 512;
                const int row = f >> 2, u = (f & 3) * 8;
                size_t vidx = ((size_t)b * BDIM + row) * SLEN + k0 + u;
                uint32_t dst = (uint32_t)(row * TSTRIDE + u) * 2;
                CP_ASYNC16(sbase + 2 * SLICE + dst, (const char*)(g_vt_hi + vidx));
                CP_ASYNC16(sbase + 3 * SLICE + dst, (const char*)(g_vt_lo + vidx));
            }
        }
    };

    const int wm = wid & 3;
    const int wn = wid >> 2;
    const int mbase = wm * 32;
    const int nbase = wn * 32;

    float acc[2][4][4] = {};
    const int cn = (qt + 1) * 2;       // chunks per half
    const int c0 = half * cn;

    fill(0, c0);
    CP_COMMIT;

    for (int i = 0; i < cn; i++) {
        if (i + 1 < cn) {
            __syncthreads();
            fill((i + 1) & 1, c0 + i + 1);
            CP_COMMIT;
            CP_WAIT(1);
        } else {
            CP_WAIT(0);
        }
        __syncthreads();

        const uint32_t cb = sb + (i & 1) * TBUF;
#pragma unroll
        for (int kc = 0; kc < 2; kc++) {
            const int k0 = kc * 16;
            uint32_t bhi[8], blo[8];
#pragma unroll
            for (int jp = 0; jp < 2; jp++) {
                load_b_pair<TSTRIDE>(cb + 2 * SLICE, nbase + jp * 16, k0, lane, &bhi[jp * 4]);
                load_b_pair<TSTRIDE>(cb + 3 * SLICE, nbase + jp * 16, k0, lane, &blo[jp * 4]);
            }
#pragma unroll
            for (int mt = 0; mt < 2; mt++) {
                uint32_t ahi[4], alo[4];
                load_a_frag<TSTRIDE>(cb, mbase + mt * 16, k0, lane, ahi);
                load_a_frag<TSTRIDE>(cb + SLICE, mbase + mt * 16, k0, lane, alo);
#pragma unroll
                for (int nt = 0; nt < 4; nt++) {
                    MMA_BF16(acc[mt][nt], ahi[0], ahi[1], ahi[2], ahi[3], bhi[nt * 2], bhi[nt * 2 + 1]);
                    MMA_BF16(acc[mt][nt], ahi[0], ahi[1], ahi[2], ahi[3], blo[nt * 2], blo[nt * 2 + 1]);
                    MMA_BF16(acc[mt][nt], alo[0], alo[1], alo[2], alo[3], bhi[nt * 2], bhi[nt * 2 + 1]);
                }
            }
        }
    }

    // accumulate ctx via atomics (2 halves contribute per output element)
    float* og = ctx + ((size_t)b * SLEN + qt * 128) * BDIM;
#pragma unroll
    for (int mt = 0; mt < 2; mt++) {
        const int r0 = mbase + mt * 16 + (lane >> 2);
#pragma unroll
        for (int nt = 0; nt < 4; nt++) {
            const int col = nbase + nt * 8 + (lane & 3) * 2;
#pragma unroll
            for (int h = 0; h < 2; h++) {
                const int r = r0 + h * 8;
                atomicAdd(og + (size_t)r * BDIM + col + 0, acc[mt][nt][h * 2 + 0]);
                atomicAdd(og + (size_t)r * BDIM + col + 1, acc[mt][nt][h * 2 + 1]);
            }
        }
    }
}

// ============================== launch ======================================
extern "C" void kernel_launch(void* const* d_in, const int* in_sizes, int n_in,
                              void* d_out, int out_size)
{
    const float* q = (const float*)d_in[0];
    const float* k = (const float*)d_in[1];
    const float* v = (const float*)d_in[2];

    float* ctx  = (float*)d_out;
    float* attn = ctx + (size_t)NBATCH * SLEN * BDIM;

    cudaFuncSetAttribute(vt_kernel,    cudaFuncAttributeMaxDynamicSharedMemorySize, VT_SMEM);
    cudaFuncSetAttribute(score_kernel, cudaFuncAttributeMaxDynamicSharedMemorySize, TSMEM);
    cudaFuncSetAttribute(pv_kernel,    cudaFuncAttributeMaxDynamicSharedMemorySize, TSMEM);

    const int ztot = (NBATCH * SLEN * BDIM + NBATCH * SLEN) / 4;   // float4 count
    zsum_kernel<<<(ztot + 255) / 256, 256>>>(ctx);
    split_qk_kernel<<<(NBATCH * SLEN * BDIM) / (256 * 8), 256>>>(q, k);
    vt_kernel<<<dim3(SLEN / 128, NBATCH), 256, VT_SMEM>>>(v);
    score_kernel<<<dim3(SLEN / 128, SLEN / 128, NBATCH), 256, TSMEM>>>(attn);
    pv_kernel<<<dim3(2, SLEN / 128, NBATCH), 512, TSMEM>>>(attn, ctx);
}

// round 17
// speedup vs baseline: 1.3606x; 1.0089x over previous
#include <cuda_runtime.h>
#include <cuda_bf16.h>
#include <cstdint>
#include <cstddef>

#define SLEN 2048
#define BDIM 128
#define NBATCH 32
#define INV_TEMP 0.08838834764831845f   // 1/sqrt(128)

// ======================= device scratch (no cudaMalloc) ====================
__device__ __nv_bfloat16 g_q_hi[(size_t)NBATCH * SLEN * BDIM];
__device__ __nv_bfloat16 g_q_lo[(size_t)NBATCH * SLEN * BDIM];
__device__ __nv_bfloat16 g_k_hi[(size_t)NBATCH * SLEN * BDIM];
__device__ __nv_bfloat16 g_k_lo[(size_t)NBATCH * SLEN * BDIM];
__device__ __nv_bfloat16 g_vt_hi[(size_t)NBATCH * BDIM * SLEN];
__device__ __nv_bfloat16 g_vt_lo[(size_t)NBATCH * BDIM * SLEN];
__device__ float g_rowsum[(size_t)NBATCH * SLEN];

// pv work table: qt>=8 split 4-way, 4<=qt<=7 split 2-way, qt<4 unsplit.
// per-CTA chunks = (qt+1)*4/np <= 16  (near-uniform waves)
#define PV_ENTRIES 44
__constant__ uint8_t c_pv_qt[PV_ENTRIES] = {
    15,15,15,15, 14,14,14,14, 13,13,13,13, 12,12,12,12,
    11,11,11,11, 10,10,10,10,  9, 9, 9, 9,  8, 8, 8, 8,
     7, 7,  6, 6,  5, 5,  4, 4,  3, 2, 1, 0};
__constant__ uint8_t c_pv_part[PV_ENTRIES] = {
    0,1,2,3, 0,1,2,3, 0,1,2,3, 0,1,2,3,
    0,1,2,3, 0,1,2,3, 0,1,2,3, 0,1,2,3,
    0,1, 0,1, 0,1, 0,1, 0, 0, 0, 0};
__constant__ uint8_t c_pv_np[PV_ENTRIES] = {
    4,4,4,4, 4,4,4,4, 4,4,4,4, 4,4,4,4,
    4,4,4,4, 4,4,4,4, 4,4,4,4, 4,4,4,4,
    2,2, 2,2, 2,2, 2,2, 1, 1, 1, 1};

// =========================== helpers =======================================
__device__ __forceinline__ uint32_t smem_u32(const void* p) {
    uint32_t a;
    asm("{ .reg .u64 t; cvta.to.shared.u64 t, %1; cvt.u32.u64 %0, t; }"
        : "=r"(a) : "l"(p));
    return a;
}

#define LDSM_X4(r0, r1, r2, r3, addr) \
    asm volatile("ldmatrix.sync.aligned.m8n8.x4.shared.b16 {%0,%1,%2,%3}, [%4];" \
        : "=r"(r0), "=r"(r1), "=r"(r2), "=r"(r3) : "r"(addr))

#define MMA_BF16(c, a0, a1, a2, a3, b0, b1) \
    asm volatile("mma.sync.aligned.m16n8k16.row.col.f32.bf16.bf16.f32 " \
        "{%0,%1,%2,%3}, {%4,%5,%6,%7}, {%8,%9}, {%0,%1,%2,%3};" \
        : "+f"((c)[0]), "+f"((c)[1]), "+f"((c)[2]), "+f"((c)[3]) \
        : "r"(a0), "r"(a1), "r"(a2), "r"(a3), "r"(b0), "r"(b1))

#define CP_ASYNC16(dst, src) \
    asm volatile("cp.async.cg.shared.global [%0], [%1], 16;" \
        :: "r"(dst), "l"(src) : "memory")
#define CP_COMMIT  asm volatile("cp.async.commit_group;" ::: "memory")
#define CP_WAIT(n) asm volatile("cp.async.wait_group %0;" :: "n"(n) : "memory")

template <int STRIDE>
__device__ __forceinline__ void load_a_frag(uint32_t base, int mrow, int k0,
                                            int lane, uint32_t* a) {
    uint32_t off = (uint32_t)((mrow + (lane & 15)) * STRIDE + k0 + ((lane >> 4) << 3));
    LDSM_X4(a[0], a[1], a[2], a[3], base + (off << 1));
}

template <int STRIDE>
__device__ __forceinline__ void load_b_pair(uint32_t base, int nrow, int k0,
                                            int lane, uint32_t* b) {
    int g = lane >> 3;
    uint32_t off = (uint32_t)((nrow + ((g & 2) << 2) + (lane & 7)) * STRIDE
                              + k0 + ((g & 1) << 3));
    LDSM_X4(b[0], b[1], b[2], b[3], base + (off << 1));
}

// split 8 fp32 -> bf16 hi/lo packed uint4s
__device__ __forceinline__ void cvt8(const float4& x0, const float4& x1,
                                     uint4& hi, uint4& lo) {
    float v[8] = {x0.x, x0.y, x0.z, x0.w, x1.x, x1.y, x1.z, x1.w};
    uint32_t hb[8], lb[8];
#pragma unroll
    for (int j = 0; j < 8; j++) {
        __nv_bfloat16 h = __float2bfloat16(v[j]);
        float r = v[j] - __bfloat162float(h);
        __nv_bfloat16 l = __float2bfloat16(r);
        hb[j] = (uint32_t)__bfloat16_as_ushort(h);
        lb[j] = (uint32_t)__bfloat16_as_ushort(l);
    }
    hi = make_uint4(hb[0] | (hb[1] << 16), hb[2] | (hb[3] << 16),
                    hb[4] | (hb[5] << 16), hb[6] | (hb[7] << 16));
    lo = make_uint4(lb[0] | (lb[1] << 16), lb[2] | (lb[3] << 16),
                    lb[4] | (lb[5] << 16), lb[6] | (lb[7] << 16));
}

// fast exp on FMA/ALU pipes (no MUFU): 2^f poly deg-6, rel err ~1e-7
__device__ __forceinline__ float fast_exp(float x) {
    x = fmaxf(x, -87.0f);
    float y = x * 1.4426950408889634f;
    float t = y + 12582912.0f;
    int   ni = __float_as_int(t) - 0x4B400000;
    float nf = t - 12582912.0f;
    float f = y - nf;
    float p = 1.5403530e-4f;
    p = fmaf(p, f, 1.3333558e-3f);
    p = fmaf(p, f, 9.6181291e-3f);
    p = fmaf(p, f, 5.5504109e-2f);
    p = fmaf(p, f, 2.4022651e-1f);
    p = fmaf(p, f, 6.9314718e-1f);
    p = fmaf(p, f, 1.0f);
    return p * __int_as_float((ni + 127) << 23);
}

// key permutation inside each 16-row group: fragment slots {2g,2g+1,2g+8,2g+9}
// hold keys {4g,4g+1,4g+2,4g+3}  ->  lane stores one contiguous float4
__device__ __forceinline__ int kperm(int n) {
    return (n & ~15) | (n & 1) | (((n >> 3) & 1) << 1) | (((n >> 1) & 3) << 2);
}

// shared tile geometry: K-chunks of 32, 4 slices per buffer, double buffered
#define TSTRIDE 40                          // bf16 elems per row (32 + 8 pad)
#define SLICE   (128 * TSTRIDE * 2)         // 10240 B
#define TBUF    (4 * SLICE)                 // 40960 B
#define TSMEM   (2 * TBUF)                  // 81920 B -> 2 CTAs/SM

// =============== prep 0: zero row sums + zero ctx ===========================
__global__ __launch_bounds__(256) void zsum_kernel(float* __restrict__ ctx) {
    const size_t i4 = ((size_t)blockIdx.x * 256 + threadIdx.x) * 4;
    const float4 z = make_float4(0.f, 0.f, 0.f, 0.f);
    const size_t ctx_elems = (size_t)NBATCH * SLEN * BDIM;
    if (i4 < ctx_elems)
        *reinterpret_cast<float4*>(ctx + i4) = z;
    else if (i4 < ctx_elems + (size_t)NBATCH * SLEN)
        *reinterpret_cast<float4*>(g_rowsum + (i4 - ctx_elems)) = z;
}

// =============== prep 1: split Q,K into bf16 hi/lo scratch ==================
__global__ __launch_bounds__(256) void split_qk_kernel(
    const float* __restrict__ Q, const float* __restrict__ K)
{
    const size_t base = ((size_t)blockIdx.x * 256 + threadIdx.x) * 8;
    uint4 hi, lo;
    float4 x0 = *reinterpret_cast<const float4*>(Q + base);
    float4 x1 = *reinterpret_cast<const float4*>(Q + base + 4);
    cvt8(x0, x1, hi, lo);
    *reinterpret_cast<uint4*>(g_q_hi + base) = hi;
    *reinterpret_cast<uint4*>(g_q_lo + base) = lo;
    x0 = *reinterpret_cast<const float4*>(K + base);
    x1 = *reinterpret_cast<const float4*>(K + base + 4);
    cvt8(x0, x1, hi, lo);
    *reinterpret_cast<uint4*>(g_k_hi + base) = hi;
    *reinterpret_cast<uint4*>(g_k_lo + base) = lo;
}

// =============== prep 2: V -> V^T bf16 hi/lo scratch ========================
#define VT_SMEM (128 * 132 * 4)
__global__ __launch_bounds__(256) void vt_kernel(const float* __restrict__ V) {
    extern __shared__ float ts[];   // [128][132]
    const int st = blockIdx.x, b = blockIdx.y, tid = threadIdx.x;
    const int s0 = st * 128;
    const float* vg = V + ((size_t)b * SLEN + s0) * BDIM;
#pragma unroll
    for (int i = 0; i < 16; i++) {
        int flat = tid + i * 256;
        int row = flat >> 5, c4 = flat & 31;
        float4 x = *reinterpret_cast<const float4*>(vg + (size_t)row * BDIM + c4 * 4);
        *reinterpret_cast<float4*>(ts + row * 132 + c4 * 4) = x;
    }
    __syncthreads();
#pragma unroll
    for (int i = 0; i < 8; i++) {
        int flat = tid + i * 256;
        int d = flat >> 4, sg = (flat & 15) * 8;
        uint32_t hb[8], lb[8];
#pragma unroll
        for (int j = 0; j < 8; j++) {
            float v = ts[(sg + j) * 132 + d];
            __nv_bfloat16 h = __float2bfloat16(v);
            float r = v - __bfloat162float(h);
            __nv_bfloat16 l = __float2bfloat16(r);
            hb[j] = (uint32_t)__bfloat16_as_ushort(h);
            lb[j] = (uint32_t)__bfloat16_as_ushort(l);
        }
        uint4 hi = make_uint4(hb[0] | (hb[1] << 16), hb[2] | (hb[3] << 16),
                              hb[4] | (hb[5] << 16), hb[6] | (hb[7] << 16));
        uint4 lo = make_uint4(lb[0] | (lb[1] << 16), lb[2] | (lb[3] << 16),
                              lb[4] | (lb[5] << 16), lb[6] | (lb[7] << 16));
        size_t idx = ((size_t)b * BDIM + d) * SLEN + s0 + sg;
        *reinterpret_cast<uint4*>(g_vt_hi + idx) = hi;
        *reinterpret_cast<uint4*>(g_vt_lo + idx) = lo;
    }
}

// ====== kernel 1: E = exp(causal(QK^T/sqrt(D))) + per-row sum atomics =======
// 256 threads, 2 CTAs/SM, warp tile 32x64, double-buffered k-chunks of 32.
// K rows permuted in smem (kperm) so the epilogue emits contiguous STG.128.
__global__ __launch_bounds__(256, 2) void score_kernel(float* __restrict__ attn)
{
    extern __shared__ char sm[];
    const int kt = blockIdx.x, qt = blockIdx.y, b = blockIdx.z;
    const int tid = threadIdx.x, wid = tid >> 5, lane = tid & 31;

    float* out = attn + (size_t)b * SLEN * SLEN + (size_t)(qt * 128) * SLEN + kt * 128;

    if (kt > qt) {   // fully masked tile -> zeros
        const float4 z = make_float4(0.f, 0.f, 0.f, 0.f);
#pragma unroll
        for (int it = 0; it < 16; it++) {
            const int flat = tid + it * 256;
            const int r = flat >> 5, c4 = flat & 31;
            *reinterpret_cast<float4*>(out + (size_t)r * SLEN + c4 * 4) = z;
        }
        return;
    }

    const uint32_t sb = smem_u32(sm);
    const size_t qoff = ((size_t)b * SLEN + qt * 128) * BDIM;
    const size_t koff = ((size_t)b * SLEN + kt * 128) * BDIM;
    const __nv_bfloat16* srcs[4] = {g_q_hi + qoff, g_q_lo + qoff,
                                    g_k_hi + koff, g_k_lo + koff};

    auto fill = [&](int buf, int c) {
#pragma unroll
        for (int i = 0; i < 8; i++) {
            const int flat = tid + i * 256;
            const int tile = flat >> 9;
            const int idx  = flat & 511;
            const int row  = idx >> 2, u = idx & 3;
            const int srow = (tile >= 2) ? kperm(row) : row;
            uint32_t dst = sb + buf * TBUF + tile * SLICE
                         + (uint32_t)(row * TSTRIDE + u * 8) * 2;
            CP_ASYNC16(dst, srcs[tile] + (size_t)srow * BDIM + c * 32 + u * 8);
        }
    };

    const int wm = wid & 3;
    const int wn = wid >> 2;
    const int mbase = wm * 32;
    const int nbase = wn * 64;

    float acc[2][8][4] = {};

    fill(0, 0);
    CP_COMMIT;
    for (int c = 0; c < 4; c++) {
        if (c + 1 < 4) {
            __syncthreads();
            fill((c + 1) & 1, c + 1);
            CP_COMMIT;
            CP_WAIT(1);
        } else {
            CP_WAIT(0);
        }
        __syncthreads();

        const uint32_t cb = sb + (c & 1) * TBUF;
#pragma unroll
        for (int kc = 0; kc < 2; kc++) {
            const int k0 = kc * 16;
            uint32_t ahi[2][4], alo[2][4];
#pragma unroll
            for (int mt = 0; mt < 2; mt++) {
                load_a_frag<TSTRIDE>(cb,         mbase + mt * 16, k0, lane, ahi[mt]);
                load_a_frag<TSTRIDE>(cb + SLICE, mbase + mt * 16, k0, lane, alo[mt]);
            }
#pragma unroll
            for (int jp = 0; jp < 4; jp++) {
                uint32_t bhi[4], blo[4];
                load_b_pair<TSTRIDE>(cb + 2 * SLICE, nbase + jp * 16, k0, lane, bhi);
                load_b_pair<TSTRIDE>(cb + 3 * SLICE, nbase + jp * 16, k0, lane, blo);
                const int n0 = jp * 2, n1 = jp * 2 + 1;
                MMA_BF16(acc[0][n0], ahi[0][0], ahi[0][1], ahi[0][2], ahi[0][3], bhi[0], bhi[1]);
                MMA_BF16(acc[0][n1], ahi[0][0], ahi[0][1], ahi[0][2], ahi[0][3], bhi[2], bhi[3]);
                MMA_BF16(acc[1][n0], ahi[1][0], ahi[1][1], ahi[1][2], ahi[1][3], bhi[0], bhi[1]);
                MMA_BF16(acc[1][n1], ahi[1][0], ahi[1][1], ahi[1][2], ahi[1][3], bhi[2], bhi[3]);
                MMA_BF16(acc[0][n0], ahi[0][0], ahi[0][1], ahi[0][2], ahi[0][3], blo[0], blo[1]);
                MMA_BF16(acc[0][n1], ahi[0][0], ahi[0][1], ahi[0][2], ahi[0][3], blo[2], blo[3]);
                MMA_BF16(acc[1][n0], ahi[1][0], ahi[1][1], ahi[1][2], ahi[1][3], blo[0], blo[1]);
                MMA_BF16(acc[1][n1], ahi[1][0], ahi[1][1], ahi[1][2], ahi[1][3], blo[2], blo[3]);
                MMA_BF16(acc[0][n0], alo[0][0], alo[0][1], alo[0][2], alo[0][3], bhi[0], bhi[1]);
                MMA_BF16(acc[0][n1], alo[0][0], alo[0][1], alo[0][2], alo[0][3], bhi[2], bhi[3]);
                MMA_BF16(acc[1][n0], alo[1][0], alo[1][1], alo[1][2], alo[1][3], bhi[0], bhi[1]);
                MMA_BF16(acc[1][n1], alo[1][0], alo[1][1], alo[1][2], alo[1][3], bhi[2], bhi[3]);
            }
        }
    }

    const bool diag = (kt == qt);
    float rsum[2][2] = {};
#pragma unroll
    for (int mt = 0; mt < 2; mt++) {
        const int r0 = mbase + mt * 16 + (lane >> 2);
#pragma unroll
        for (int jp = 0; jp < 4; jp++) {
            const int colb = nbase + jp * 16 + (lane & 3) * 4;
            const int ne = jp * 2, no = jp * 2 + 1;
#pragma unroll
            for (int h = 0; h < 2; h++) {
                const int r = r0 + h * 8;
                float v0 = fast_exp(acc[mt][ne][h * 2 + 0] * INV_TEMP);
                float v1 = fast_exp(acc[mt][ne][h * 2 + 1] * INV_TEMP);
                float v2 = fast_exp(acc[mt][no][h * 2 + 0] * INV_TEMP);
                float v3 = fast_exp(acc[mt][no][h * 2 + 1] * INV_TEMP);
                if (diag) {
                    if (colb + 0 > r) v0 = 0.f;
                    if (colb + 1 > r) v1 = 0.f;
                    if (colb + 2 > r) v2 = 0.f;
                    if (colb + 3 > r) v3 = 0.f;
                }
                rsum[mt][h] += (v0 + v1) + (v2 + v3);
                *reinterpret_cast<float4*>(out + (size_t)r * SLEN + colb) =
                    make_float4(v0, v1, v2, v3);
            }
        }
    }
#pragma unroll
    for (int mt = 0; mt < 2; mt++)
#pragma unroll
        for (int h = 0; h < 2; h++) {
            rsum[mt][h] += __shfl_xor_sync(0xffffffffu, rsum[mt][h], 1);
            rsum[mt][h] += __shfl_xor_sync(0xffffffffu, rsum[mt][h], 2);
        }
    if ((lane & 3) == 0) {
        float* rs = g_rowsum + (size_t)b * SLEN + qt * 128;
#pragma unroll
        for (int mt = 0; mt < 2; mt++)
#pragma unroll
            for (int h = 0; h < 2; h++)
                atomicAdd(rs + mbase + mt * 16 + (lane >> 2) + h * 8, rsum[mt][h]);
    }
}

// ====== kernel 2: ctx += (E/rowsum) @ V; also writes normalized attn ========
// Balanced variable key-split via constant work table: per-CTA work <= 16
// chunks of 32 keys. 512 threads, 2 CTAs/SM, warp tile 32x32, ctx atomics.
__global__ __launch_bounds__(512, 2) void pv_kernel(
    float* __restrict__ attn,
    float* __restrict__ ctx)
{
    extern __shared__ char sm[];
    __shared__ float sinv[128];
    const int e  = blockIdx.x;
    const int qt = c_pv_qt[e];
    const int b  = blockIdx.y;
    const int tid = threadIdx.x, wid = tid >> 5, lane = tid & 31;

    const int cn = ((qt + 1) * 4) / c_pv_np[e];   // chunks for this part
    const int c0 = c_pv_part[e] * cn;

    const uint32_t sb = smem_u32(sm);
    float* pg = attn + (size_t)b * SLEN * SLEN + (size_t)(qt * 128) * SLEN;

    if (tid < 128)
        sinv[tid] = 1.0f / g_rowsum[(size_t)b * SLEN + qt * 128 + tid];
    __syncthreads();

    auto fill = [&](int buf, int c) {
        const int k0 = c * 32;
        char* base = sm + buf * TBUF;
        const uint32_t sbase = sb + buf * TBUF;
#pragma unroll
        for (int i = 0; i < 2; i++) {
            const int flat = tid + i * 512;
            if (flat < 512) {
                const int row = flat >> 2, g8 = (flat & 3) * 8;
                float* prow = pg + (size_t)row * SLEN + k0 + g8;
                float4 x0 = *reinterpret_cast<const float4*>(prow);
                float4 x1 = *reinterpret_cast<const float4*>(prow + 4);
                const float inv = sinv[row];
                x0.x *= inv; x0.y *= inv; x0.z *= inv; x0.w *= inv;
                x1.x *= inv; x1.y *= inv; x1.z *= inv; x1.w *= inv;
                *reinterpret_cast<float4*>(prow)     = x0;
                *reinterpret_cast<float4*>(prow + 4) = x1;
                uint4 hi, lo;
                cvt8(x0, x1, hi, lo);
                uint32_t dst = (uint32_t)(row * TSTRIDE + g8) * 2;
                *reinterpret_cast<uint4*>(base + dst)         = hi;
                *reinterpret_cast<uint4*>(base + SLICE + dst) = lo;
            } else {
                const int f = flat - 512;
                const int row = f >> 2, u = (f & 3) * 8;
                size_t vidx = ((size_t)b * BDIM + row) * SLEN + k0 + u;
                uint32_t dst = (uint32_t)(row * TSTRIDE + u) * 2;
                CP_ASYNC16(sbase + 2 * SLICE + dst, (const char*)(g_vt_hi + vidx));
                CP_ASYNC16(sbase + 3 * SLICE + dst, (const char*)(g_vt_lo + vidx));
            }
        }
    };

    const int wm = wid & 3;
    const int wn = wid >> 2;
    const int mbase = wm * 32;
    const int nbase = wn * 32;

    float acc[2][4][4] = {};

    fill(0, c0);
    CP_COMMIT;

    for (int i = 0; i < cn; i++) {
        if (i + 1 < cn) {
            __syncthreads();
            fill((i + 1) & 1, c0 + i + 1);
            CP_COMMIT;
            CP_WAIT(1);
        } else {
            CP_WAIT(0);
        }
        __syncthreads();

        const uint32_t cb = sb + (i & 1) * TBUF;
#pragma unroll
        for (int kc = 0; kc < 2; kc++) {
            const int k0 = kc * 16;
            uint32_t bhi[8], blo[8];
#pragma unroll
            for (int jp = 0; jp < 2; jp++) {
                load_b_pair<TSTRIDE>(cb + 2 * SLICE, nbase + jp * 16, k0, lane, &bhi[jp * 4]);
                load_b_pair<TSTRIDE>(cb + 3 * SLICE, nbase + jp * 16, k0, lane, &blo[jp * 4]);
            }
#pragma unroll
            for (int mt = 0; mt < 2; mt++) {
                uint32_t ahi[4], alo[4];
                load_a_frag<TSTRIDE>(cb, mbase + mt * 16, k0, lane, ahi);
                load_a_frag<TSTRIDE>(cb + SLICE, mbase + mt * 16, k0, lane, alo);
#pragma unroll
                for (int nt = 0; nt < 4; nt++) {
                    MMA_BF16(acc[mt][nt], ahi[0], ahi[1], ahi[2], ahi[3], bhi[nt * 2], bhi[nt * 2 + 1]);
                    MMA_BF16(acc[mt][nt], ahi[0], ahi[1], ahi[2], ahi[3], blo[nt * 2], blo[nt * 2 + 1]);
                    MMA_BF16(acc[mt][nt], alo[0], alo[1], alo[2], alo[3], bhi[nt * 2], bhi[nt * 2 + 1]);
                }
            }
        }
    }

    // accumulate ctx via atomics (np parts contribute per output element)
    float* og = ctx + ((size_t)b * SLEN + qt * 128) * BDIM;
#pragma unroll
    for (int mt = 0; mt < 2; mt++) {
        const int r0 = mbase + mt * 16 + (lane >> 2);
#pragma unroll
        for (int nt = 0; nt < 4; nt++) {
            const int col = nbase + nt * 8 + (lane & 3) * 2;
#pragma unroll
            for (int h = 0; h < 2; h++) {
                const int r = r0 + h * 8;
                atomicAdd(og + (size_t)r * BDIM + col + 0, acc[mt][nt][h * 2 + 0]);
                atomicAdd(og + (size_t)r * BDIM + col + 1, acc[mt][nt][h * 2 + 1]);
            }
        }
    }
}

// ============================== launch ======================================
extern "C" void kernel_launch(void* const* d_in, const int* in_sizes, int n_in,
                              void* d_out, int out_size)
{
    const float* q = (const float*)d_in[0];
    const float* k = (const float*)d_in[1];
    const float* v = (const float*)d_in[2];

    float* ctx  = (float*)d_out;
    float* attn = ctx + (size_t)NBATCH * SLEN * BDIM;

    cudaFuncSetAttribute(vt_kernel,    cudaFuncAttributeMaxDynamicSharedMemorySize, VT_SMEM);
    cudaFuncSetAttribute(score_kernel, cudaFuncAttributeMaxDynamicSharedMemorySize, TSMEM);
    cudaFuncSetAttribute(pv_kernel,    cudaFuncAttributeMaxDynamicSharedMemorySize, TSMEM);

    const int ztot = (NBATCH * SLEN * BDIM + NBATCH * SLEN) / 4;   // float4 count
    zsum_kernel<<<(ztot + 255) / 256, 256>>>(ctx);
    split_qk_kernel<<<(NBATCH * SLEN * BDIM) / (256 * 8), 256>>>(q, k);
    vt_kernel<<<dim3(SLEN / 128, NBATCH), 256, VT_SMEM>>>(v);
    score_kernel<<<dim3(SLEN / 128, SLEN / 128, NBATCH), 256, TSMEM>>>(attn);
    pv_kernel<<<dim3(PV_ENTRIES, NBATCH), 512, TSMEM>>>(attn, ctx);
}